// round 9
// baseline (speedup 1.0000x reference)
#include <cuda_runtime.h>
#include <cuda_bf16.h>
#include <cstdint>
#include <math.h>

#define BB 2
#define TT 2048
#define DD 2048
#define HH 32
#define HD 64
#define MM (BB*TT)          // 4096

// ---------------- scratch (device globals; allocation is forbidden) ----------
__device__ __nv_bfloat16 g_xhi[(size_t)MM * DD];
__device__ __nv_bfloat16 g_xlo[(size_t)MM * DD];
__device__ __nv_bfloat16 g_whi[4][(size_t)DD * DD];
__device__ __nv_bfloat16 g_wlo[4][(size_t)DD * DD];
__device__ __nv_bfloat16 g_qhi[(size_t)MM * DD];
__device__ __nv_bfloat16 g_qlo[(size_t)MM * DD];
__device__ __nv_bfloat16 g_khi[(size_t)MM * DD];
__device__ __nv_bfloat16 g_klo[(size_t)MM * DD];
__device__ __nv_bfloat16 g_vhi[(size_t)MM * DD];
__device__ __nv_bfloat16 g_vlo[(size_t)MM * DD];
__device__ __nv_bfloat16 g_chi[(size_t)MM * DD];
__device__ __nv_bfloat16 g_clo[(size_t)MM * DD];

// ---------------- helpers ----------------------------------------------------
__device__ __forceinline__ uint32_t smem_u32(const void* p) {
    uint32_t a;
    asm("{ .reg .u64 t; cvta.to.shared.u64 t, %1; cvt.u32.u64 %0, t; }" : "=r"(a) : "l"(p));
    return a;
}
__device__ __forceinline__ void ldsm4(uint32_t* r, uint32_t addr) {
    asm volatile("ldmatrix.sync.aligned.m8n8.x4.shared.b16 {%0,%1,%2,%3}, [%4];"
        : "=r"(r[0]), "=r"(r[1]), "=r"(r[2]), "=r"(r[3]) : "r"(addr));
}
__device__ __forceinline__ void ldsm4t(uint32_t* r, uint32_t addr) {
    asm volatile("ldmatrix.sync.aligned.m8n8.x4.trans.shared.b16 {%0,%1,%2,%3}, [%4];"
        : "=r"(r[0]), "=r"(r[1]), "=r"(r[2]), "=r"(r[3]) : "r"(addr));
}
__device__ __forceinline__ void mma16816(float* d, const uint32_t* a, uint32_t b0, uint32_t b1) {
    asm volatile("mma.sync.aligned.m16n8k16.row.col.f32.bf16.bf16.f32 "
        "{%0,%1,%2,%3}, {%4,%5,%6,%7}, {%8,%9}, {%0,%1,%2,%3};"
        : "+f"(d[0]), "+f"(d[1]), "+f"(d[2]), "+f"(d[3])
        : "r"(a[0]), "r"(a[1]), "r"(a[2]), "r"(a[3]), "r"(b0), "r"(b1));
}
#define CP_ASYNC16(saddr, gptr) \
    asm volatile("cp.async.cg.shared.global [%0], [%1], 16;" :: "r"(saddr), "l"(gptr))
#define CP_COMMIT() asm volatile("cp.async.commit_group;" ::: "memory")

__device__ __forceinline__ uint32_t pack_hi(float x, float y) {
    __nv_bfloat162 h = __floats2bfloat162_rn(x, y);
    return *(uint32_t*)&h;
}
__device__ __forceinline__ uint32_t pack_lo(float x, float y, uint32_t hi) {
    __nv_bfloat162 h = *(__nv_bfloat162*)&hi;
    __nv_bfloat162 l = __floats2bfloat162_rn(x - __bfloat162float(h.x),
                                             y - __bfloat162float(h.y));
    return *(uint32_t*)&l;
}

// ---------------- split fp32 -> bf16 hi/lo ------------------------------------
__global__ void split_kernel(const float* __restrict__ x,
                             __nv_bfloat16* __restrict__ hi,
                             __nv_bfloat16* __restrict__ lo, size_t n4)
{
    size_t i = ((size_t)blockIdx.x * blockDim.x + threadIdx.x);
    if (i >= n4) return;
    float4 v = ((const float4*)x)[i];
    uint32_t h0 = pack_hi(v.x, v.y), h1 = pack_hi(v.z, v.w);
    uint32_t l0 = pack_lo(v.x, v.y, h0), l1 = pack_lo(v.z, v.w, h1);
    ((uint32_t*)hi)[i * 2 + 0] = h0;
    ((uint32_t*)hi)[i * 2 + 1] = h1;
    ((uint32_t*)lo)[i * 2 + 0] = l0;
    ((uint32_t*)lo)[i * 2 + 1] = l1;
}

// ---------------- mma.sync GEMM (bf16x3), 3-stage cp.async -------------------
// C[M, n-slab] = A[M,K] * B[N,K]^T + bias.  B rows indexed globally by
// blockIdx.x so Q/K/V (contiguous weights) fuse into one launch.
#define GBK 32
#define NCH (DD / GBK)              // 64 k-chunks
#define ROWB 80
#define TILEB (128 * ROWB)          // 10240 B
#define STAGEB (4 * TILEB)          // 40960 B
#define NSTAGE 3
#define GEMM_SMEM (NSTAGE * STAGEB) // 122880 B

__global__ __launch_bounds__(256)
void gemm_mma_bf16x3(const __nv_bfloat16* __restrict__ Ahi, const __nv_bfloat16* __restrict__ Alo,
                     const __nv_bfloat16* __restrict__ Wh,  const __nv_bfloat16* __restrict__ Wl,
                     const float* __restrict__ b0p, const float* __restrict__ b1p,
                     const float* __restrict__ b2p,
                     __nv_bfloat16* __restrict__ o0h, __nv_bfloat16* __restrict__ o0l,
                     __nv_bfloat16* __restrict__ o1h, __nv_bfloat16* __restrict__ o1l,
                     __nv_bfloat16* __restrict__ o2h, __nv_bfloat16* __restrict__ o2l,
                     float* __restrict__ Cf)
{
    extern __shared__ char sm[];
    const uint32_t sb = smem_u32(sm);
    const int tid  = threadIdx.x;
    const int wid  = tid >> 5, lane = tid & 31;
    const int bm0  = blockIdx.y * 128;
    const int mat  = blockIdx.x >> 4;          // 0..2 (0 for single-matrix)
    const int col0 = (blockIdx.x & 15) * 128;  // col within output matrix
    const int wm   = (wid & 1) * 64;
    const int wn   = (wid >> 1) * 32;

    const float* bias = (mat == 0) ? b0p : (mat == 1) ? b1p : b2p;
    __nv_bfloat16* outh = (mat == 0) ? o0h : (mat == 1) ? o1h : o2h;
    __nv_bfloat16* outl = (mat == 0) ? o0l : (mat == 1) ? o1l : o2l;

    const __nv_bfloat16* gp0 = Ahi + (size_t)bm0 * DD;
    const __nv_bfloat16* gp1 = Alo + (size_t)bm0 * DD;
    const __nv_bfloat16* gp2 = Wh + (size_t)blockIdx.x * 128 * DD;  // global B rows
    const __nv_bfloat16* gp3 = Wl + (size_t)blockIdx.x * 128 * DD;

    const int lr0 = tid >> 2;
    const int lc  = tid & 3;

    auto load_stage = [&](int c, int s) {
        const int k0 = c * GBK;
        const uint32_t sdst = sb + s * STAGEB;
        #pragma unroll
        for (int j = 0; j < 2; j++) {
            const int row = lr0 + j * 64;
            const uint32_t sa = sdst + row * ROWB + lc * 16;
            const size_t go = (size_t)row * DD + k0 + lc * 8;
            CP_ASYNC16(sa + 0 * TILEB, gp0 + go);
            CP_ASYNC16(sa + 1 * TILEB, gp1 + go);
            CP_ASYNC16(sa + 2 * TILEB, gp2 + go);
            CP_ASYNC16(sa + 3 * TILEB, gp3 + go);
        }
        CP_COMMIT();
    };

    float acc[4][4][4];
    #pragma unroll
    for (int i = 0; i < 4; i++)
        #pragma unroll
        for (int j = 0; j < 4; j++)
            #pragma unroll
            for (int r = 0; r < 4; r++) acc[i][j][r] = 0.f;

    const int r8  = lane & 7;
    const int qq  = lane >> 3;
    const int lrow  = (qq & 1) * 8 + r8;
    const int lcol8 = (qq >> 1);

    load_stage(0, 0);
    load_stage(1, 1);

    int stage = 0;
    for (int c = 0; c < NCH; c++) {
        if (c + 2 < NCH) {
            asm volatile("cp.async.wait_group 1;" ::: "memory");
        } else {
            asm volatile("cp.async.wait_group 0;" ::: "memory");
        }
        __syncthreads();
        if (c + 2 < NCH) {
            int s2 = stage + 2; if (s2 >= NSTAGE) s2 -= NSTAGE;
            load_stage(c + 2, s2);
        }

        const uint32_t st = sb + stage * STAGEB;
        #pragma unroll
        for (int ks = 0; ks < 2; ks++) {
            const int kb = (ks * 16 + lcol8 * 8) * 2;
            uint32_t bh[2][4], bl[2][4];
            #pragma unroll
            for (int nh = 0; nh < 2; nh++) {
                const uint32_t boff = (uint32_t)((wn + nh * 16 + lrow) * ROWB + kb);
                ldsm4(bh[nh], st + 2 * TILEB + boff);
                ldsm4(bl[nh], st + 3 * TILEB + boff);
            }
            uint32_t ah[4][4], al[4][4];
            #pragma unroll
            for (int mt = 0; mt < 4; mt++) {
                const uint32_t aoff = (uint32_t)((wm + mt * 16 + lrow) * ROWB + kb);
                ldsm4(ah[mt], st + 0 * TILEB + aoff);
                ldsm4(al[mt], st + 1 * TILEB + aoff);
            }
            #pragma unroll
            for (int mt = 0; mt < 4; mt++)
                #pragma unroll
                for (int nh = 0; nh < 2; nh++)
                    #pragma unroll
                    for (int nn = 0; nn < 2; nn++) {
                        float* d = acc[mt][nh * 2 + nn];
                        mma16816(d, ah[mt], bh[nh][nn], bh[nh][nn + 2]);
                        mma16816(d, al[mt], bh[nh][nn], bh[nh][nn + 2]);
                        mma16816(d, ah[mt], bl[nh][nn], bl[nh][nn + 2]);
                    }
        }
        stage++; if (stage >= NSTAGE) stage -= NSTAGE;
    }

    const int erow = lane >> 2;
    const int ecol = (lane & 3) * 2;
    #pragma unroll
    for (int mt = 0; mt < 4; mt++) {
        #pragma unroll
        for (int nt = 0; nt < 4; nt++) {
            const int col = col0 + wn + nt * 8 + ecol;
            const float b0 = bias[col], b1 = bias[col + 1];
            const int row0 = bm0 + wm + mt * 16 + erow;
            float v00 = acc[mt][nt][0] + b0, v01 = acc[mt][nt][1] + b1;
            float v10 = acc[mt][nt][2] + b0, v11 = acc[mt][nt][3] + b1;
            if (Cf) {
                *(float2*)(Cf + (size_t)row0 * DD + col)       = make_float2(v00, v01);
                *(float2*)(Cf + (size_t)(row0 + 8) * DD + col) = make_float2(v10, v11);
            } else {
                uint32_t h0 = pack_hi(v00, v01), h1 = pack_hi(v10, v11);
                *(uint32_t*)(outh + (size_t)row0 * DD + col)       = h0;
                *(uint32_t*)(outh + (size_t)(row0 + 8) * DD + col) = h1;
                *(uint32_t*)(outl + (size_t)row0 * DD + col)       = pack_lo(v00, v01, h0);
                *(uint32_t*)(outl + (size_t)(row0 + 8) * DD + col) = pack_lo(v10, v11, h1);
            }
        }
    }
}

// ---------------- Flash attention on mma.sync (bf16x3, causal) ---------------
#define AQ 128
#define AKV 64
#define AROW 144
#define QAREA 18432                 // 128 * AROW
#define KVAREA 9216                 // 64 * AROW
#define ATT_SMEM (2 * QAREA)

__global__ __launch_bounds__(256)
void attn_mma(const __nv_bfloat16* __restrict__ Qhi, const __nv_bfloat16* __restrict__ Qlo,
              const __nv_bfloat16* __restrict__ Khi, const __nv_bfloat16* __restrict__ Klo,
              const __nv_bfloat16* __restrict__ Vhi, const __nv_bfloat16* __restrict__ Vlo,
              __nv_bfloat16* __restrict__ Chi, __nv_bfloat16* __restrict__ Clo)
{
    extern __shared__ char smc[];
    const uint32_t sb = smem_u32(smc);
    const int tid = threadIdx.x;
    const int wid = tid >> 5, lane = tid & 31;
    const int bh  = blockIdx.y;
    const int b   = bh >> 5, h = bh & 31;
    const int qblk = gridDim.x - 1 - blockIdx.x;   // heavy blocks launch first
    const int q0  = qblk * AQ;
    const size_t base = ((size_t)b * TT) * DD + (size_t)h * HD;

    const int r8  = lane & 7;
    const int qq  = lane >> 3;
    const int lrow  = (qq & 1) * 8 + r8;
    const int lcol8 = (qq >> 1);

    // ---- load Q hi/lo into smem ----
    {
        const int rr = tid >> 1;
        const int ch = (tid & 1) * 4;
        const size_t gq = base + (size_t)(q0 + rr) * DD;
        #pragma unroll
        for (int cc = 0; cc < 4; cc++) {
            *(uint4*)(smc + rr * AROW + (ch + cc) * 16) =
                *(const uint4*)(Qhi + gq + (ch + cc) * 8);
            *(uint4*)(smc + QAREA + rr * AROW + (ch + cc) * 16) =
                *(const uint4*)(Qlo + gq + (ch + cc) * 8);
        }
    }
    __syncthreads();

    uint32_t qh[4][4], ql[4][4];
    #pragma unroll
    for (int ks = 0; ks < 4; ks++) {
        uint32_t qa = sb + (uint32_t)((wid * 16 + lrow) * AROW + (ks * 16 + lcol8 * 8) * 2);
        ldsm4(qh[ks], qa);
        ldsm4(ql[ks], qa + QAREA);
    }
    __syncthreads();

    float m0 = -1e30f, m1 = -1e30f, l0 = 0.f, l1 = 0.f;
    float acc[8][4];
    #pragma unroll
    for (int i = 0; i < 8; i++)
        #pragma unroll
        for (int j = 0; j < 4; j++) acc[i][j] = 0.f;

    const int ntiles = (q0 + AQ) / AKV;
    const int row0g = q0 + wid * 16 + (lane >> 2);

    for (int kt = 0; kt < ntiles; kt++) {
        const int k0 = kt * AKV;
        {
            const int rr = tid >> 2;
            const int ch = (tid & 3) * 2;
            const size_t gk = base + (size_t)(k0 + rr) * DD;
            #pragma unroll
            for (int cc = 0; cc < 2; cc++) {
                const int c16 = ch + cc;
                *(uint4*)(smc + 0 * KVAREA + rr * AROW + c16 * 16) =
                    *(const uint4*)(Khi + gk + c16 * 8);
                *(uint4*)(smc + 1 * KVAREA + rr * AROW + c16 * 16) =
                    *(const uint4*)(Klo + gk + c16 * 8);
                *(uint4*)(smc + 2 * KVAREA + rr * AROW + c16 * 16) =
                    *(const uint4*)(Vhi + gk + c16 * 8);
                *(uint4*)(smc + 3 * KVAREA + rr * AROW + c16 * 16) =
                    *(const uint4*)(Vlo + gk + c16 * 8);
            }
        }
        __syncthreads();

        float s[8][4];
        #pragma unroll
        for (int i = 0; i < 8; i++)
            #pragma unroll
            for (int j = 0; j < 4; j++) s[i][j] = 0.f;

        #pragma unroll
        for (int ks = 0; ks < 4; ks++) {
            uint32_t kh[4][4], kl[4][4];
            #pragma unroll
            for (int np = 0; np < 4; np++) {
                uint32_t ka = sb + (uint32_t)((np * 16 + lrow) * AROW + (ks * 16 + lcol8 * 8) * 2);
                ldsm4(kh[np], ka);
                ldsm4(kl[np], ka + KVAREA);
            }
            #pragma unroll
            for (int np = 0; np < 4; np++)
                #pragma unroll
                for (int nn = 0; nn < 2; nn++) {
                    float* d = s[np * 2 + nn];
                    mma16816(d, qh[ks], kh[np][nn], kh[np][nn + 2]);
                    mma16816(d, ql[ks], kh[np][nn], kh[np][nn + 2]);
                    mma16816(d, qh[ks], kl[np][nn], kl[np][nn + 2]);
                }
        }

        const bool masked = (kt >= ntiles - 2);
        #pragma unroll
        for (int nt = 0; nt < 8; nt++) {
            #pragma unroll
            for (int j = 0; j < 4; j++) s[nt][j] *= 0.125f;
            if (masked) {
                int col = k0 + nt * 8 + (lane & 3) * 2;
                if (col     > row0g)     s[nt][0] = -1e30f;
                if (col + 1 > row0g)     s[nt][1] = -1e30f;
                if (col     > row0g + 8) s[nt][2] = -1e30f;
                if (col + 1 > row0g + 8) s[nt][3] = -1e30f;
            }
        }

        float rm0 = -1e30f, rm1 = -1e30f;
        #pragma unroll
        for (int nt = 0; nt < 8; nt++) {
            rm0 = fmaxf(rm0, fmaxf(s[nt][0], s[nt][1]));
            rm1 = fmaxf(rm1, fmaxf(s[nt][2], s[nt][3]));
        }
        rm0 = fmaxf(rm0, __shfl_xor_sync(0xffffffffu, rm0, 1));
        rm0 = fmaxf(rm0, __shfl_xor_sync(0xffffffffu, rm0, 2));
        rm1 = fmaxf(rm1, __shfl_xor_sync(0xffffffffu, rm1, 1));
        rm1 = fmaxf(rm1, __shfl_xor_sync(0xffffffffu, rm1, 2));
        float mn0 = fmaxf(m0, rm0), mn1 = fmaxf(m1, rm1);
        float co0 = __expf(m0 - mn0), co1 = __expf(m1 - mn1);
        float rs0 = 0.f, rs1 = 0.f;
        #pragma unroll
        for (int nt = 0; nt < 8; nt++) {
            s[nt][0] = __expf(s[nt][0] - mn0); rs0 += s[nt][0];
            s[nt][1] = __expf(s[nt][1] - mn0); rs0 += s[nt][1];
            s[nt][2] = __expf(s[nt][2] - mn1); rs1 += s[nt][2];
            s[nt][3] = __expf(s[nt][3] - mn1); rs1 += s[nt][3];
        }
        rs0 += __shfl_xor_sync(0xffffffffu, rs0, 1);
        rs0 += __shfl_xor_sync(0xffffffffu, rs0, 2);
        rs1 += __shfl_xor_sync(0xffffffffu, rs1, 1);
        rs1 += __shfl_xor_sync(0xffffffffu, rs1, 2);
        l0 = l0 * co0 + rs0; m0 = mn0;
        l1 = l1 * co1 + rs1; m1 = mn1;
        #pragma unroll
        for (int nt = 0; nt < 8; nt++) {
            acc[nt][0] *= co0; acc[nt][1] *= co0;
            acc[nt][2] *= co1; acc[nt][3] *= co1;
        }

        uint32_t ph[4][4], pl[4][4];
        #pragma unroll
        for (int kc = 0; kc < 4; kc++) {
            float* sa  = s[2 * kc];
            float* sbq = s[2 * kc + 1];
            ph[kc][0] = pack_hi(sa[0], sa[1]);   pl[kc][0] = pack_lo(sa[0], sa[1], ph[kc][0]);
            ph[kc][1] = pack_hi(sa[2], sa[3]);   pl[kc][1] = pack_lo(sa[2], sa[3], ph[kc][1]);
            ph[kc][2] = pack_hi(sbq[0], sbq[1]); pl[kc][2] = pack_lo(sbq[0], sbq[1], ph[kc][2]);
            ph[kc][3] = pack_hi(sbq[2], sbq[3]); pl[kc][3] = pack_lo(sbq[2], sbq[3], ph[kc][3]);
        }

        #pragma unroll
        for (int kc = 0; kc < 4; kc++) {
            #pragma unroll
            for (int np = 0; np < 4; np++) {
                uint32_t vh[4], vl[4];
                uint32_t va = sb + 2u * KVAREA +
                    (uint32_t)((kc * 16 + lrow) * AROW + (np * 16 + lcol8 * 8) * 2);
                ldsm4t(vh, va);
                ldsm4t(vl, va + KVAREA);
                #pragma unroll
                for (int nn = 0; nn < 2; nn++) {
                    float* d = acc[np * 2 + nn];
                    mma16816(d, ph[kc], vh[nn * 2], vh[nn * 2 + 1]);
                    mma16816(d, pl[kc], vh[nn * 2], vh[nn * 2 + 1]);
                    mma16816(d, ph[kc], vl[nn * 2], vl[nn * 2 + 1]);
                }
            }
        }
        __syncthreads();
    }

    const float inv0 = 1.f / l0, inv1 = 1.f / l1;
    const int rw0 = q0 + wid * 16 + (lane >> 2);
    #pragma unroll
    for (int nt = 0; nt < 8; nt++) {
        const int colg = nt * 8 + (lane & 3) * 2;
        float v00 = acc[nt][0] * inv0, v01 = acc[nt][1] * inv0;
        float v10 = acc[nt][2] * inv1, v11 = acc[nt][3] * inv1;
        uint32_t h0 = pack_hi(v00, v01), h1 = pack_hi(v10, v11);
        *(uint32_t*)(Chi + base + (size_t)rw0 * DD + colg)       = h0;
        *(uint32_t*)(Chi + base + (size_t)(rw0 + 8) * DD + colg) = h1;
        *(uint32_t*)(Clo + base + (size_t)rw0 * DD + colg)       = pack_lo(v00, v01, h0);
        *(uint32_t*)(Clo + base + (size_t)(rw0 + 8) * DD + colg) = pack_lo(v10, v11, h1);
    }
}

// ---------------- launch ------------------------------------------------------
extern "C" void kernel_launch(void* const* d_in, const int* in_sizes, int n_in,
                              void* d_out, int out_size)
{
    const float* X  = (const float*)d_in[0];
    const float* Wq = (const float*)d_in[1];
    const float* bq = (const float*)d_in[2];
    const float* Wk = (const float*)d_in[3];
    const float* bk = (const float*)d_in[4];
    const float* Wv = (const float*)d_in[5];
    const float* bv = (const float*)d_in[6];
    const float* Wo = (const float*)d_in[7];
    const float* bo = (const float*)d_in[8];
    float* out = (float*)d_out;

    __nv_bfloat16 *xhi, *xlo, *whi, *wlo;
    __nv_bfloat16 *qhi, *qlo, *khi, *klo, *vhi, *vlo, *chi, *clo;
    cudaGetSymbolAddress((void**)&xhi, g_xhi);
    cudaGetSymbolAddress((void**)&xlo, g_xlo);
    cudaGetSymbolAddress((void**)&whi, g_whi);
    cudaGetSymbolAddress((void**)&wlo, g_wlo);
    cudaGetSymbolAddress((void**)&qhi, g_qhi);
    cudaGetSymbolAddress((void**)&qlo, g_qlo);
    cudaGetSymbolAddress((void**)&khi, g_khi);
    cudaGetSymbolAddress((void**)&klo, g_klo);
    cudaGetSymbolAddress((void**)&vhi, g_vhi);
    cudaGetSymbolAddress((void**)&vlo, g_vlo);
    cudaGetSymbolAddress((void**)&chi, g_chi);
    cudaGetSymbolAddress((void**)&clo, g_clo);

    cudaFuncSetAttribute(gemm_mma_bf16x3, cudaFuncAttributeMaxDynamicSharedMemorySize, GEMM_SMEM);
    cudaFuncSetAttribute(attn_mma, cudaFuncAttributeMaxDynamicSharedMemorySize, ATT_SMEM);

    const size_t nX4 = (size_t)MM * DD / 4;
    const size_t nW4 = (size_t)DD * DD / 4;
    const size_t WS  = (size_t)DD * DD;

    split_kernel<<<(unsigned)((nX4 + 255) / 256), 256>>>(X,  xhi, xlo, nX4);
    split_kernel<<<(unsigned)((nW4 + 255) / 256), 256>>>(Wq, whi + 0 * WS, wlo + 0 * WS, nW4);
    split_kernel<<<(unsigned)((nW4 + 255) / 256), 256>>>(Wk, whi + 1 * WS, wlo + 1 * WS, nW4);
    split_kernel<<<(unsigned)((nW4 + 255) / 256), 256>>>(Wv, whi + 2 * WS, wlo + 2 * WS, nW4);
    split_kernel<<<(unsigned)((nW4 + 255) / 256), 256>>>(Wo, whi + 3 * WS, wlo + 3 * WS, nW4);

    // Fused QKV: B rows span Wq|Wk|Wv (contiguous in g_whi). grid (48, 32).
    gemm_mma_bf16x3<<<dim3(48, MM / 128), 256, GEMM_SMEM>>>(
        xhi, xlo, whi, wlo, bq, bk, bv,
        qhi, qlo, khi, klo, vhi, vlo, nullptr);

    attn_mma<<<dim3(TT / AQ, BB * HH), 256, ATT_SMEM>>>(qhi, qlo, khi, klo, vhi, vlo, chi, clo);

    // Output projection: single matrix (grid.x = 16 -> mat = 0), fp32 out.
    gemm_mma_bf16x3<<<dim3(16, MM / 128), 256, GEMM_SMEM>>>(
        chi, clo, whi + 3 * WS, wlo + 3 * WS, bo, bo, bo,
        nullptr, nullptr, nullptr, nullptr, nullptr, nullptr, out);
}

// round 10
// speedup vs baseline: 1.0771x; 1.0771x over previous
#include <cuda_runtime.h>
#include <cuda_bf16.h>
#include <cstdint>
#include <math.h>

#define BB 2
#define TT 2048
#define DD 2048
#define HH 32
#define HD 64
#define MM (BB*TT)          // 4096

// ---------------- scratch (device globals; allocation is forbidden) ----------
__device__ __nv_bfloat16 g_xhi[(size_t)MM * DD];
__device__ __nv_bfloat16 g_xlo[(size_t)MM * DD];
__device__ __nv_bfloat16 g_whi[4][(size_t)DD * DD];
__device__ __nv_bfloat16 g_wlo[4][(size_t)DD * DD];
__device__ __nv_bfloat16 g_qhi[(size_t)MM * DD];
__device__ __nv_bfloat16 g_qlo[(size_t)MM * DD];
__device__ __nv_bfloat16 g_khi[(size_t)MM * DD];
__device__ __nv_bfloat16 g_klo[(size_t)MM * DD];
__device__ __nv_bfloat16 g_vhi[(size_t)MM * DD];
__device__ __nv_bfloat16 g_vlo[(size_t)MM * DD];
__device__ __nv_bfloat16 g_chi[(size_t)MM * DD];
__device__ __nv_bfloat16 g_clo[(size_t)MM * DD];

// ---------------- helpers ----------------------------------------------------
__device__ __forceinline__ uint32_t smem_u32(const void* p) {
    uint32_t a;
    asm("{ .reg .u64 t; cvta.to.shared.u64 t, %1; cvt.u32.u64 %0, t; }" : "=r"(a) : "l"(p));
    return a;
}
__device__ __forceinline__ void ldsm4(uint32_t* r, uint32_t addr) {
    asm volatile("ldmatrix.sync.aligned.m8n8.x4.shared.b16 {%0,%1,%2,%3}, [%4];"
        : "=r"(r[0]), "=r"(r[1]), "=r"(r[2]), "=r"(r[3]) : "r"(addr));
}
__device__ __forceinline__ void ldsm4t(uint32_t* r, uint32_t addr) {
    asm volatile("ldmatrix.sync.aligned.m8n8.x4.trans.shared.b16 {%0,%1,%2,%3}, [%4];"
        : "=r"(r[0]), "=r"(r[1]), "=r"(r[2]), "=r"(r[3]) : "r"(addr));
}
__device__ __forceinline__ void mma16816(float* d, const uint32_t* a, uint32_t b0, uint32_t b1) {
    asm volatile("mma.sync.aligned.m16n8k16.row.col.f32.bf16.bf16.f32 "
        "{%0,%1,%2,%3}, {%4,%5,%6,%7}, {%8,%9}, {%0,%1,%2,%3};"
        : "+f"(d[0]), "+f"(d[1]), "+f"(d[2]), "+f"(d[3])
        : "r"(a[0]), "r"(a[1]), "r"(a[2]), "r"(a[3]), "r"(b0), "r"(b1));
}
#define CP_ASYNC16(saddr, gptr) \
    asm volatile("cp.async.cg.shared.global [%0], [%1], 16;" :: "r"(saddr), "l"(gptr))
#define CP_COMMIT() asm volatile("cp.async.commit_group;" ::: "memory")

__device__ __forceinline__ uint32_t pack_hi(float x, float y) {
    __nv_bfloat162 h = __floats2bfloat162_rn(x, y);
    return *(uint32_t*)&h;
}
__device__ __forceinline__ uint32_t pack_lo(float x, float y, uint32_t hi) {
    __nv_bfloat162 h = *(__nv_bfloat162*)&hi;
    __nv_bfloat162 l = __floats2bfloat162_rn(x - __bfloat162float(h.x),
                                             y - __bfloat162float(h.y));
    return *(uint32_t*)&l;
}

// ---------------- split fp32 -> bf16 hi/lo ------------------------------------
__global__ void split_kernel(const float* __restrict__ x,
                             __nv_bfloat16* __restrict__ hi,
                             __nv_bfloat16* __restrict__ lo, size_t n4)
{
    size_t i = ((size_t)blockIdx.x * blockDim.x + threadIdx.x);
    if (i >= n4) return;
    float4 v = ((const float4*)x)[i];
    uint32_t h0 = pack_hi(v.x, v.y), h1 = pack_hi(v.z, v.w);
    uint32_t l0 = pack_lo(v.x, v.y, h0), l1 = pack_lo(v.z, v.w, h1);
    ((uint32_t*)hi)[i * 2 + 0] = h0;
    ((uint32_t*)hi)[i * 2 + 1] = h1;
    ((uint32_t*)lo)[i * 2 + 0] = l0;
    ((uint32_t*)lo)[i * 2 + 1] = l1;
}

// ---------------- mma.sync GEMM (R7 structure, known-good) -------------------
// C[M,N] = A[M,K]*B[N,K]^T + bias.  128x128 tile, BK=32, 2-stage cp.async.
#define GBK 32
#define NCH (DD / GBK)              // 64 k-chunks
#define ROWB 80
#define TILEB (128 * ROWB)          // 10240 B
#define STAGEB (4 * TILEB)          // 40960 B
#define GEMM_SMEM (2 * STAGEB)      // 81920 B

__global__ __launch_bounds__(256)
void gemm_mma_bf16x3(const __nv_bfloat16* __restrict__ Ahi, const __nv_bfloat16* __restrict__ Alo,
                     const __nv_bfloat16* __restrict__ Bhi, const __nv_bfloat16* __restrict__ Blo,
                     const float* __restrict__ bias, float* __restrict__ Cf,
                     __nv_bfloat16* __restrict__ Chi, __nv_bfloat16* __restrict__ Clo)
{
    extern __shared__ char sm[];
    const uint32_t sb = smem_u32(sm);
    const int tid  = threadIdx.x;
    const int wid  = tid >> 5, lane = tid & 31;
    const int bm0  = blockIdx.y * 128, bn0 = blockIdx.x * 128;
    const int wm   = (wid & 1) * 64;
    const int wn   = (wid >> 1) * 32;

    const __nv_bfloat16* gp0 = Ahi + (size_t)bm0 * DD;
    const __nv_bfloat16* gp1 = Alo + (size_t)bm0 * DD;
    const __nv_bfloat16* gp2 = Bhi + (size_t)bn0 * DD;
    const __nv_bfloat16* gp3 = Blo + (size_t)bn0 * DD;

    const int lr0 = tid >> 2;
    const int lc  = tid & 3;

    auto load_stage = [&](int c, int s) {
        const int k0 = c * GBK;
        const uint32_t sdst = sb + s * STAGEB;
        #pragma unroll
        for (int j = 0; j < 2; j++) {
            const int row = lr0 + j * 64;
            const uint32_t sa = sdst + row * ROWB + lc * 16;
            const size_t go = (size_t)row * DD + k0 + lc * 8;
            CP_ASYNC16(sa + 0 * TILEB, gp0 + go);
            CP_ASYNC16(sa + 1 * TILEB, gp1 + go);
            CP_ASYNC16(sa + 2 * TILEB, gp2 + go);
            CP_ASYNC16(sa + 3 * TILEB, gp3 + go);
        }
        CP_COMMIT();
    };

    float acc[4][4][4];
    #pragma unroll
    for (int i = 0; i < 4; i++)
        #pragma unroll
        for (int j = 0; j < 4; j++)
            #pragma unroll
            for (int r = 0; r < 4; r++) acc[i][j][r] = 0.f;

    const int r8  = lane & 7;
    const int qq  = lane >> 3;
    const int lrow  = (qq & 1) * 8 + r8;
    const int lcol8 = (qq >> 1);

    load_stage(0, 0);

    for (int c = 0; c < NCH; c++) {
        if (c + 1 < NCH) {
            load_stage(c + 1, (c + 1) & 1);
            asm volatile("cp.async.wait_group 1;" ::: "memory");
        } else {
            asm volatile("cp.async.wait_group 0;" ::: "memory");
        }
        __syncthreads();

        const uint32_t st = sb + (c & 1) * STAGEB;
        #pragma unroll
        for (int ks = 0; ks < 2; ks++) {
            const int kb = (ks * 16 + lcol8 * 8) * 2;
            uint32_t bh[2][4], bl[2][4];
            #pragma unroll
            for (int nh = 0; nh < 2; nh++) {
                const uint32_t boff = (uint32_t)((wn + nh * 16 + lrow) * ROWB + kb);
                ldsm4(bh[nh], st + 2 * TILEB + boff);
                ldsm4(bl[nh], st + 3 * TILEB + boff);
            }
            uint32_t ah[4][4], al[4][4];
            #pragma unroll
            for (int mt = 0; mt < 4; mt++) {
                const uint32_t aoff = (uint32_t)((wm + mt * 16 + lrow) * ROWB + kb);
                ldsm4(ah[mt], st + 0 * TILEB + aoff);
                ldsm4(al[mt], st + 1 * TILEB + aoff);
            }
            #pragma unroll
            for (int mt = 0; mt < 4; mt++)
                #pragma unroll
                for (int nh = 0; nh < 2; nh++)
                    #pragma unroll
                    for (int nn = 0; nn < 2; nn++) {
                        float* d = acc[mt][nh * 2 + nn];
                        mma16816(d, ah[mt], bh[nh][nn], bh[nh][nn + 2]);
                        mma16816(d, al[mt], bh[nh][nn], bh[nh][nn + 2]);
                        mma16816(d, ah[mt], bl[nh][nn], bl[nh][nn + 2]);
                    }
        }
        __syncthreads();
    }

    const int erow = lane >> 2;
    const int ecol = (lane & 3) * 2;
    #pragma unroll
    for (int mt = 0; mt < 4; mt++) {
        #pragma unroll
        for (int nt = 0; nt < 4; nt++) {
            const int col = bn0 + wn + nt * 8 + ecol;
            const float b0 = bias[col], b1 = bias[col + 1];
            const int row0 = bm0 + wm + mt * 16 + erow;
            float v00 = acc[mt][nt][0] + b0, v01 = acc[mt][nt][1] + b1;
            float v10 = acc[mt][nt][2] + b0, v11 = acc[mt][nt][3] + b1;
            if (Cf) {
                *(float2*)(Cf + (size_t)row0 * DD + col)       = make_float2(v00, v01);
                *(float2*)(Cf + (size_t)(row0 + 8) * DD + col) = make_float2(v10, v11);
            } else {
                uint32_t h0 = pack_hi(v00, v01), h1 = pack_hi(v10, v11);
                *(uint32_t*)(Chi + (size_t)row0 * DD + col)       = h0;
                *(uint32_t*)(Chi + (size_t)(row0 + 8) * DD + col) = h1;
                *(uint32_t*)(Clo + (size_t)row0 * DD + col)       = pack_lo(v00, v01, h0);
                *(uint32_t*)(Clo + (size_t)(row0 + 8) * DD + col) = pack_lo(v10, v11, h1);
            }
        }
    }
}

// ---------------- Flash attention, cp.async 2-stage KV pipeline --------------
// CTA: 128 q-rows of one (b,h). 8 warps x 16 rows. KV tiles of 64.
// Buf0 recycles the Q staging area once Q frags are register-resident.
#define AQ 128
#define AKV 64
#define AROW 144
#define QAREA 18432                 // 128 * AROW
#define KVAREA 9216                 // 64 * AROW
#define KVSTAGE (4 * KVAREA)        // 36864 (Khi|Klo|Vhi|Vlo)
#define ATT_SMEM (2 * KVSTAGE)      // 73728 B

__global__ __launch_bounds__(256)
void attn_mma(const __nv_bfloat16* __restrict__ Qhi, const __nv_bfloat16* __restrict__ Qlo,
              const __nv_bfloat16* __restrict__ Khi, const __nv_bfloat16* __restrict__ Klo,
              const __nv_bfloat16* __restrict__ Vhi, const __nv_bfloat16* __restrict__ Vlo,
              __nv_bfloat16* __restrict__ Chi, __nv_bfloat16* __restrict__ Clo)
{
    extern __shared__ char smc[];
    const uint32_t sb = smem_u32(smc);
    const int tid = threadIdx.x;
    const int wid = tid >> 5, lane = tid & 31;
    const int bh  = blockIdx.y;
    const int b   = bh >> 5, h = bh & 31;
    const int qblk = gridDim.x - 1 - blockIdx.x;   // heavy blocks launch first
    const int q0  = qblk * AQ;
    const size_t base = ((size_t)b * TT) * DD + (size_t)h * HD;

    const int r8  = lane & 7;
    const int qq  = lane >> 3;
    const int lrow  = (qq & 1) * 8 + r8;
    const int lcol8 = (qq >> 1);

    const int ntiles = (q0 + AQ) / AKV;   // >= 2
    const int row0g = q0 + wid * 16 + (lane >> 2);

    // KV stage loader (cp.async, 8 chunks/thread)
    const int krr = tid >> 2;           // 0..63
    const int kch = (tid & 3) * 2;      // chunk base 0,2,4,6
    auto load_kv = [&](int kt, uint32_t bufoff) {
        const size_t gk = base + (size_t)(kt * AKV + krr) * DD;
        #pragma unroll
        for (int cc = 0; cc < 2; cc++) {
            const int c16 = kch + cc;
            const uint32_t sa = sb + bufoff + krr * AROW + c16 * 16;
            const size_t go = gk + c16 * 8;
            CP_ASYNC16(sa + 0 * KVAREA, Khi + go);
            CP_ASYNC16(sa + 1 * KVAREA, Klo + go);
            CP_ASYNC16(sa + 2 * KVAREA, Vhi + go);
            CP_ASYNC16(sa + 3 * KVAREA, Vlo + go);
        }
        CP_COMMIT();
    };

    // ---- issue KV tile 0 into buf1 (overlaps the whole Q prologue) ----
    load_kv(0, KVSTAGE);

    // ---- stage Q hi/lo (buf0 area), grab fragments, then free buf0 ----
    {
        const int rr = tid >> 1;
        const int ch = (tid & 1) * 4;
        const size_t gq = base + (size_t)(q0 + rr) * DD;
        #pragma unroll
        for (int cc = 0; cc < 4; cc++) {
            *(uint4*)(smc + rr * AROW + (ch + cc) * 16) =
                *(const uint4*)(Qhi + gq + (ch + cc) * 8);
            *(uint4*)(smc + QAREA + rr * AROW + (ch + cc) * 16) =
                *(const uint4*)(Qlo + gq + (ch + cc) * 8);
        }
    }
    __syncthreads();

    uint32_t qh[4][4], ql[4][4];
    #pragma unroll
    for (int ks = 0; ks < 4; ks++) {
        uint32_t qa = sb + (uint32_t)((wid * 16 + lrow) * AROW + (ks * 16 + lcol8 * 8) * 2);
        ldsm4(qh[ks], qa);
        ldsm4(ql[ks], qa + QAREA);
    }
    __syncthreads();   // all warps done with buf0 (Q area) -> reusable

    float m0 = -1e30f, m1 = -1e30f, l0 = 0.f, l1 = 0.f;
    float acc[8][4];
    #pragma unroll
    for (int i = 0; i < 8; i++)
        #pragma unroll
        for (int j = 0; j < 4; j++) acc[i][j] = 0.f;

    for (int kt = 0; kt < ntiles; kt++) {
        const int k0 = kt * AKV;
        const uint32_t buf = (kt & 1) ? 0u : (uint32_t)KVSTAGE;   // kt0->buf1

        asm volatile("cp.async.wait_group 0;" ::: "memory");
        __syncthreads();   // tile kt visible to all; all warps past tile kt-1

        if (kt + 1 < ntiles)
            load_kv(kt + 1, ((kt + 1) & 1) ? 0u : (uint32_t)KVSTAGE);

        // ---- S = Q K^T (bf16x3) ----
        float s[8][4];
        #pragma unroll
        for (int i = 0; i < 8; i++)
            #pragma unroll
            for (int j = 0; j < 4; j++) s[i][j] = 0.f;

        #pragma unroll
        for (int ks = 0; ks < 4; ks++) {
            uint32_t kh[4][4], kl[4][4];
            #pragma unroll
            for (int np = 0; np < 4; np++) {
                uint32_t ka = sb + buf +
                    (uint32_t)((np * 16 + lrow) * AROW + (ks * 16 + lcol8 * 8) * 2);
                ldsm4(kh[np], ka);
                ldsm4(kl[np], ka + KVAREA);
            }
            #pragma unroll
            for (int np = 0; np < 4; np++)
                #pragma unroll
                for (int nn = 0; nn < 2; nn++) {
                    float* d = s[np * 2 + nn];
                    mma16816(d, qh[ks], kh[np][nn], kh[np][nn + 2]);
                    mma16816(d, ql[ks], kh[np][nn], kh[np][nn + 2]);
                    mma16816(d, qh[ks], kl[np][nn], kl[np][nn + 2]);
                }
        }

        // ---- scale + causal mask ----
        const bool masked = (kt >= ntiles - 2);
        #pragma unroll
        for (int nt = 0; nt < 8; nt++) {
            #pragma unroll
            for (int j = 0; j < 4; j++) s[nt][j] *= 0.125f;
            if (masked) {
                int col = k0 + nt * 8 + (lane & 3) * 2;
                if (col     > row0g)     s[nt][0] = -1e30f;
                if (col + 1 > row0g)     s[nt][1] = -1e30f;
                if (col     > row0g + 8) s[nt][2] = -1e30f;
                if (col + 1 > row0g + 8) s[nt][3] = -1e30f;
            }
        }

        // ---- online softmax (rows r and r+8) ----
        float rm0 = -1e30f, rm1 = -1e30f;
        #pragma unroll
        for (int nt = 0; nt < 8; nt++) {
            rm0 = fmaxf(rm0, fmaxf(s[nt][0], s[nt][1]));
            rm1 = fmaxf(rm1, fmaxf(s[nt][2], s[nt][3]));
        }
        rm0 = fmaxf(rm0, __shfl_xor_sync(0xffffffffu, rm0, 1));
        rm0 = fmaxf(rm0, __shfl_xor_sync(0xffffffffu, rm0, 2));
        rm1 = fmaxf(rm1, __shfl_xor_sync(0xffffffffu, rm1, 1));
        rm1 = fmaxf(rm1, __shfl_xor_sync(0xffffffffu, rm1, 2));
        float mn0 = fmaxf(m0, rm0), mn1 = fmaxf(m1, rm1);
        float co0 = __expf(m0 - mn0), co1 = __expf(m1 - mn1);
        float rs0 = 0.f, rs1 = 0.f;
        #pragma unroll
        for (int nt = 0; nt < 8; nt++) {
            s[nt][0] = __expf(s[nt][0] - mn0); rs0 += s[nt][0];
            s[nt][1] = __expf(s[nt][1] - mn0); rs0 += s[nt][1];
            s[nt][2] = __expf(s[nt][2] - mn1); rs1 += s[nt][2];
            s[nt][3] = __expf(s[nt][3] - mn1); rs1 += s[nt][3];
        }
        rs0 += __shfl_xor_sync(0xffffffffu, rs0, 1);
        rs0 += __shfl_xor_sync(0xffffffffu, rs0, 2);
        rs1 += __shfl_xor_sync(0xffffffffu, rs1, 1);
        rs1 += __shfl_xor_sync(0xffffffffu, rs1, 2);
        l0 = l0 * co0 + rs0; m0 = mn0;
        l1 = l1 * co1 + rs1; m1 = mn1;
        #pragma unroll
        for (int nt = 0; nt < 8; nt++) {
            acc[nt][0] *= co0; acc[nt][1] *= co0;
            acc[nt][2] *= co1; acc[nt][3] *= co1;
        }

        // ---- pack P (S accumulator frags -> A operand frags), hi/lo ----
        uint32_t ph[4][4], pl[4][4];
        #pragma unroll
        for (int kc = 0; kc < 4; kc++) {
            float* sa  = s[2 * kc];
            float* sbq = s[2 * kc + 1];
            ph[kc][0] = pack_hi(sa[0], sa[1]);   pl[kc][0] = pack_lo(sa[0], sa[1], ph[kc][0]);
            ph[kc][1] = pack_hi(sa[2], sa[3]);   pl[kc][1] = pack_lo(sa[2], sa[3], ph[kc][1]);
            ph[kc][2] = pack_hi(sbq[0], sbq[1]); pl[kc][2] = pack_lo(sbq[0], sbq[1], ph[kc][2]);
            ph[kc][3] = pack_hi(sbq[2], sbq[3]); pl[kc][3] = pack_lo(sbq[2], sbq[3], ph[kc][3]);
        }

        // ---- acc += P V (bf16x3), V via ldmatrix.trans ----
        #pragma unroll
        for (int kc = 0; kc < 4; kc++) {
            #pragma unroll
            for (int np = 0; np < 4; np++) {
                uint32_t vh[4], vl[4];
                uint32_t va = sb + buf + 2u * KVAREA +
                    (uint32_t)((kc * 16 + lrow) * AROW + (np * 16 + lcol8 * 8) * 2);
                ldsm4t(vh, va);
                ldsm4t(vl, va + KVAREA);
                #pragma unroll
                for (int nn = 0; nn < 2; nn++) {
                    float* d = acc[np * 2 + nn];
                    mma16816(d, ph[kc], vh[nn * 2], vh[nn * 2 + 1]);
                    mma16816(d, pl[kc], vh[nn * 2], vh[nn * 2 + 1]);
                    mma16816(d, ph[kc], vl[nn * 2], vl[nn * 2 + 1]);
                }
            }
        }
    }

    // ---- finalize and write ctx hi/lo ----
    const float inv0 = 1.f / l0, inv1 = 1.f / l1;
    const int rw0 = q0 + wid * 16 + (lane >> 2);
    #pragma unroll
    for (int nt = 0; nt < 8; nt++) {
        const int colg = nt * 8 + (lane & 3) * 2;
        float v00 = acc[nt][0] * inv0, v01 = acc[nt][1] * inv0;
        float v10 = acc[nt][2] * inv1, v11 = acc[nt][3] * inv1;
        uint32_t h0 = pack_hi(v00, v01), h1 = pack_hi(v10, v11);
        *(uint32_t*)(Chi + base + (size_t)rw0 * DD + colg)       = h0;
        *(uint32_t*)(Chi + base + (size_t)(rw0 + 8) * DD + colg) = h1;
        *(uint32_t*)(Clo + base + (size_t)rw0 * DD + colg)       = pack_lo(v00, v01, h0);
        *(uint32_t*)(Clo + base + (size_t)(rw0 + 8) * DD + colg) = pack_lo(v10, v11, h1);
    }
}

// ---------------- launch ------------------------------------------------------
extern "C" void kernel_launch(void* const* d_in, const int* in_sizes, int n_in,
                              void* d_out, int out_size)
{
    const float* X  = (const float*)d_in[0];
    const float* Wq = (const float*)d_in[1];
    const float* bq = (const float*)d_in[2];
    const float* Wk = (const float*)d_in[3];
    const float* bk = (const float*)d_in[4];
    const float* Wv = (const float*)d_in[5];
    const float* bv = (const float*)d_in[6];
    const float* Wo = (const float*)d_in[7];
    const float* bo = (const float*)d_in[8];
    float* out = (float*)d_out;

    __nv_bfloat16 *xhi, *xlo, *whi, *wlo;
    __nv_bfloat16 *qhi, *qlo, *khi, *klo, *vhi, *vlo, *chi, *clo;
    cudaGetSymbolAddress((void**)&xhi, g_xhi);
    cudaGetSymbolAddress((void**)&xlo, g_xlo);
    cudaGetSymbolAddress((void**)&whi, g_whi);
    cudaGetSymbolAddress((void**)&wlo, g_wlo);
    cudaGetSymbolAddress((void**)&qhi, g_qhi);
    cudaGetSymbolAddress((void**)&qlo, g_qlo);
    cudaGetSymbolAddress((void**)&khi, g_khi);
    cudaGetSymbolAddress((void**)&klo, g_klo);
    cudaGetSymbolAddress((void**)&vhi, g_vhi);
    cudaGetSymbolAddress((void**)&vlo, g_vlo);
    cudaGetSymbolAddress((void**)&chi, g_chi);
    cudaGetSymbolAddress((void**)&clo, g_clo);

    cudaFuncSetAttribute(gemm_mma_bf16x3, cudaFuncAttributeMaxDynamicSharedMemorySize, GEMM_SMEM);
    cudaFuncSetAttribute(attn_mma, cudaFuncAttributeMaxDynamicSharedMemorySize, ATT_SMEM);

    const size_t nX4 = (size_t)MM * DD / 4;
    const size_t nW4 = (size_t)DD * DD / 4;
    const size_t WS  = (size_t)DD * DD;

    split_kernel<<<(unsigned)((nX4 + 255) / 256), 256>>>(X,  xhi, xlo, nX4);
    split_kernel<<<(unsigned)((nW4 + 255) / 256), 256>>>(Wq, whi + 0 * WS, wlo + 0 * WS, nW4);
    split_kernel<<<(unsigned)((nW4 + 255) / 256), 256>>>(Wk, whi + 1 * WS, wlo + 1 * WS, nW4);
    split_kernel<<<(unsigned)((nW4 + 255) / 256), 256>>>(Wv, whi + 2 * WS, wlo + 2 * WS, nW4);
    split_kernel<<<(unsigned)((nW4 + 255) / 256), 256>>>(Wo, whi + 3 * WS, wlo + 3 * WS, nW4);

    dim3 gg(DD / 128, MM / 128);   // (16, 32)
    gemm_mma_bf16x3<<<gg, 256, GEMM_SMEM>>>(xhi, xlo, whi + 0 * WS, wlo + 0 * WS, bq,
                                            nullptr, qhi, qlo);
    gemm_mma_bf16x3<<<gg, 256, GEMM_SMEM>>>(xhi, xlo, whi + 1 * WS, wlo + 1 * WS, bk,
                                            nullptr, khi, klo);
    gemm_mma_bf16x3<<<gg, 256, GEMM_SMEM>>>(xhi, xlo, whi + 2 * WS, wlo + 2 * WS, bv,
                                            nullptr, vhi, vlo);

    attn_mma<<<dim3(TT / AQ, BB * HH), 256, ATT_SMEM>>>(qhi, qlo, khi, klo, vhi, vlo, chi, clo);

    gemm_mma_bf16x3<<<gg, 256, GEMM_SMEM>>>(chi, clo, whi + 3 * WS, wlo + 3 * WS, bo,
                                            out, nullptr, nullptr);
}